// round 15
// baseline (speedup 1.0000x reference)
#include <cuda_runtime.h>
#include <cstdint>

// QuantumLikeLayer: out[b,:] = CZ_diag * (H^{⊗11} @ in[b,:]), N=2048, FWHT.
// R10 config (best measured: bench 43.26us, ncu 36.9us, ~91% of HBM roofline):
// one warp/row, 64 elems/thread packed f32x2, zero shuffles, two XOR-swizzled
// smem exchanges, CZ+2^-5.5 folded into P2's last butterfly, streaming ld/st.
// Single knob change: L2 prefetch distance halved to 1184 rows (half wave,
// 9.5MB window) to cut prefetch-vs-store L2 contention.

#define NN 2048
typedef unsigned long long u64;

// prefetch distance in rows = half a wave (ample ~4.5us lead, smaller window)
#define PF_ROWS 1184

__device__ __forceinline__ u64 pk(float x, float y) {
    u64 d; asm("mov.b64 %0,{%1,%2};" : "=l"(d) : "f"(x), "f"(y)); return d;
}
__device__ __forceinline__ void upk(u64 v, float& x, float& y) {
    asm("mov.b64 {%0,%1},%2;" : "=f"(x), "=f"(y) : "l"(v));
}
__device__ __forceinline__ u64 padd(u64 a, u64 b) {
    u64 d; asm("add.rn.f32x2 %0,%1,%2;" : "=l"(d) : "l"(a), "l"(b)); return d;
}
__device__ __forceinline__ u64 pfma(u64 a, u64 b, u64 c) {
    u64 d; asm("fma.rn.f32x2 %0,%1,%2,%3;" : "=l"(d) : "l"(a), "l"(b), "l"(c)); return d;
}
__device__ __forceinline__ u64 pmul(u64 a, u64 b) {
    u64 d; asm("mul.rn.f32x2 %0,%1,%2;" : "=l"(d) : "l"(a), "l"(b)); return d;
}

template <int M>
__device__ __forceinline__ void bfly(u64 v[32], u64 NEG1) {
#pragma unroll
    for (int r = 0; r < 32; r++) {
        if (!(r & M)) {
            u64 a = v[r], b = v[r | M];
            v[r]     = padd(a, b);
            v[r | M] = pfma(b, NEG1, a);   // a - b
        }
    }
}

__global__ void __launch_bounds__(128, 4)
fwht_cz_kernel(const float4* __restrict__ in, float4* __restrict__ out, int rows) {
    // smem per warp (8KB, 1024 u64): unit (r, col, h): idx = 32r + 2*(col ^ (r&15)) + h
    //   r = i1 + 2*i7 + 4*i8 + 8*i9 + 16*i10 ; col = i3..i6 ; h = i2 ; u64 = i0 pair
    __shared__ u64 sm[4][1024];

    const int lane = threadIdx.x & 31;
    const int wid  = threadIdx.x >> 5;
    const int row  = (blockIdx.x << 2) + wid;

    const float4* __restrict__ ip = in  + (size_t)row * (NN / 4);
    float4* __restrict__       op = out + (size_t)row * (NN / 4);
    u64* sw = sm[wid];

    // ---- L2 bulk prefetch for the row this warp slot owns half a wave later ----
    if (lane == 0) {
        int pr = row + PF_ROWS;
        if (pr < rows) {
            const float4* g = in + (size_t)pr * (NN / 4);
            asm volatile("cp.async.bulk.prefetch.L2.global [%0], %1;"
                         :: "l"(g), "r"(8192) : "memory");
        }
    }

    const u64 NEG1 = pk(-1.0f, -1.0f);
    u64 v[32];

    // ---- load (f = lane + 32j; lane = i2..i6, j = i7..i10, comps = i0,i1) ----
    // evict-first read; fuse i0 stage; pack slot = i0; reg r = i1 + 2*j
#pragma unroll
    for (int j = 0; j < 16; j++) {
        float4 q = __ldcs(&ip[lane + 32 * j]);
        v[2 * j]     = pk(q.x + q.y, q.x - q.y);   // i1 = 0
        v[2 * j + 1] = pk(q.z + q.w, q.z - q.w);   // i1 = 1
    }

    // ---- P1: i1 (bit0), i7..i10 (bits 1..4) ----
    bfly<1>(v, NEG1); bfly<2>(v, NEG1); bfly<4>(v, NEG1);
    bfly<8>(v, NEG1); bfly<16>(v, NEG1);

    // ---- exch1 write: STS.64 swizzled ----
    const int colw = lane >> 1;
    const int h    = lane & 1;
#pragma unroll
    for (int r = 0; r < 32; r++)
        sw[32 * r + 2 * (colw ^ (r & 15)) + h] = v[r];
    __syncwarp();

    // ---- exch1 read: LDS.128, thread owns region r = lane ----
    const float4* swf4 = (const float4*)sw;
    const int m15 = lane & 15;
#pragma unroll
    for (int k = 0; k < 16; k++) {
        float4 q = swf4[16 * lane + (k ^ m15)];
        v[2 * k]     = pk(q.x, q.y);   // i2 = 0
        v[2 * k + 1] = pk(q.z, q.w);   // i2 = 1
    }

    // ---- P2: i2 (bit0), i3..i5 (bits 1..3) ----
    bfly<1>(v, NEG1); bfly<2>(v, NEG1); bfly<4>(v, NEG1);
    bfly<8>(v, NEG1);

    // ---- P2 final stage (i6, reg bit 4) with CZ sign + 2^{-5.5} folded ----
    // i9,i10 = lane bits 3,4 -> sign thread-uniform; (a±b)*sc via 3 ops/pair
    {
        const float S  = 0.022097086912079608f;   // 2^{-5.5}
        float sc = ((lane & 24) == 24) ? -S : S;
        u64 sc2  = pk(sc, sc);
        u64 nsc2 = pk(-sc, -sc);
#pragma unroll
        for (int r = 0; r < 16; r++) {
            u64 a = v[r], b = v[r | 16];
            u64 t = pmul(a, sc2);
            v[r]      = pfma(b, sc2,  t);   // (a+b)*sc
            v[r | 16] = pfma(b, nsc2, t);   // (a-b)*sc
        }
    }
    __syncwarp();   // exch1 reads complete before exch2 writes

    // ---- exch2 write: STS.128 (same slots as exch1 read) ----
    float4* swf4w = (float4*)sw;
#pragma unroll
    for (int k = 0; k < 16; k++) {
        float a, b, c, d;
        upk(v[2 * k], a, b); upk(v[2 * k + 1], c, d);
        swf4w[16 * lane + (k ^ m15)] = make_float4(a, b, c, d);
    }
    __syncwarp();

    // ---- exch2 read: LDS.64 + coalesced streaming STG.128 ----
#pragma unroll
    for (int j = 0; j < 16; j++) {
        int r0 = 2 * j, r1 = 2 * j + 1;
        u64 u0 = sw[32 * r0 + 2 * (colw ^ (r0 & 15)) + h];   // i1 = 0
        u64 u1 = sw[32 * r1 + 2 * (colw ^ (r1 & 15)) + h];   // i1 = 1
        float a, b, c, d;
        upk(u0, a, b); upk(u1, c, d);
        __stcs(&op[lane + 32 * j], make_float4(a, b, c, d));
    }
}

extern "C" void kernel_launch(void* const* d_in, const int* in_sizes, int n_in,
                              void* d_out, int out_size) {
    const float4* in = (const float4*)d_in[0];
    float4* out = (float4*)d_out;
    const int rows = in_sizes[0] / NN;    // 16384
    fwht_cz_kernel<<<rows / 4, 128>>>(in, out, rows);
}

// round 16
// speedup vs baseline: 1.0904x; 1.0904x over previous
#include <cuda_runtime.h>
#include <cstdint>

// QuantumLikeLayer: out[b,:] = CZ_diag * (H^{⊗11} @ in[b,:]), N=2048, FWHT.
// FINAL (R10 config — best of 15 rounds: bench 43.26us, ncu 36.9us,
// ~91% of HBM roofline; all structural alternatives measured worse).
// One warp per row, 64 elems/thread as 32 packed f32x2 regs, zero shuffles,
// two XOR-swizzled smem exchanges (384 L1 wavefronts/row = proven floor),
// CZ sign + 2^-5.5 folded into P2's last butterfly stage, per-warp 8KB L2
// bulk prefetch one full wave ahead, streaming __ldcs/__stcs hints.

#define NN 2048
typedef unsigned long long u64;

// prefetch distance in rows = one full wave (148 SMs x 4 CTAs x 4 rows)
#define PF_ROWS 2368

__device__ __forceinline__ u64 pk(float x, float y) {
    u64 d; asm("mov.b64 %0,{%1,%2};" : "=l"(d) : "f"(x), "f"(y)); return d;
}
__device__ __forceinline__ void upk(u64 v, float& x, float& y) {
    asm("mov.b64 {%0,%1},%2;" : "=f"(x), "=f"(y) : "l"(v));
}
__device__ __forceinline__ u64 padd(u64 a, u64 b) {
    u64 d; asm("add.rn.f32x2 %0,%1,%2;" : "=l"(d) : "l"(a), "l"(b)); return d;
}
__device__ __forceinline__ u64 pfma(u64 a, u64 b, u64 c) {
    u64 d; asm("fma.rn.f32x2 %0,%1,%2,%3;" : "=l"(d) : "l"(a), "l"(b), "l"(c)); return d;
}
__device__ __forceinline__ u64 pmul(u64 a, u64 b) {
    u64 d; asm("mul.rn.f32x2 %0,%1,%2;" : "=l"(d) : "l"(a), "l"(b)); return d;
}

template <int M>
__device__ __forceinline__ void bfly(u64 v[32], u64 NEG1) {
#pragma unroll
    for (int r = 0; r < 32; r++) {
        if (!(r & M)) {
            u64 a = v[r], b = v[r | M];
            v[r]     = padd(a, b);
            v[r | M] = pfma(b, NEG1, a);   // a - b
        }
    }
}

__global__ void __launch_bounds__(128, 4)
fwht_cz_kernel(const float4* __restrict__ in, float4* __restrict__ out, int rows) {
    // smem per warp (8KB, 1024 u64): unit (r, col, h): idx = 32r + 2*(col ^ (r&15)) + h
    //   r = i1 + 2*i7 + 4*i8 + 8*i9 + 16*i10 ; col = i3..i6 ; h = i2 ; u64 = i0 pair
    __shared__ u64 sm[4][1024];

    const int lane = threadIdx.x & 31;
    const int wid  = threadIdx.x >> 5;
    const int row  = (blockIdx.x << 2) + wid;

    const float4* __restrict__ ip = in  + (size_t)row * (NN / 4);
    float4* __restrict__       op = out + (size_t)row * (NN / 4);
    u64* sw = sm[wid];

    // ---- L2 bulk prefetch for the row this warp slot owns one wave later ----
    if (lane == 0) {
        int pr = row + PF_ROWS;
        if (pr < rows) {
            const float4* g = in + (size_t)pr * (NN / 4);
            asm volatile("cp.async.bulk.prefetch.L2.global [%0], %1;"
                         :: "l"(g), "r"(8192) : "memory");
        }
    }

    const u64 NEG1 = pk(-1.0f, -1.0f);
    u64 v[32];

    // ---- load (f = lane + 32j; lane = i2..i6, j = i7..i10, comps = i0,i1) ----
    // evict-first read; fuse i0 stage; pack slot = i0; reg r = i1 + 2*j
#pragma unroll
    for (int j = 0; j < 16; j++) {
        float4 q = __ldcs(&ip[lane + 32 * j]);
        v[2 * j]     = pk(q.x + q.y, q.x - q.y);   // i1 = 0
        v[2 * j + 1] = pk(q.z + q.w, q.z - q.w);   // i1 = 1
    }

    // ---- P1: i1 (bit0), i7..i10 (bits 1..4) ----
    bfly<1>(v, NEG1); bfly<2>(v, NEG1); bfly<4>(v, NEG1);
    bfly<8>(v, NEG1); bfly<16>(v, NEG1);

    // ---- exch1 write: STS.64 swizzled ----
    const int colw = lane >> 1;
    const int h    = lane & 1;
#pragma unroll
    for (int r = 0; r < 32; r++)
        sw[32 * r + 2 * (colw ^ (r & 15)) + h] = v[r];
    __syncwarp();

    // ---- exch1 read: LDS.128, thread owns region r = lane ----
    const float4* swf4 = (const float4*)sw;
    const int m15 = lane & 15;
#pragma unroll
    for (int k = 0; k < 16; k++) {
        float4 q = swf4[16 * lane + (k ^ m15)];
        v[2 * k]     = pk(q.x, q.y);   // i2 = 0
        v[2 * k + 1] = pk(q.z, q.w);   // i2 = 1
    }

    // ---- P2: i2 (bit0), i3..i5 (bits 1..3) ----
    bfly<1>(v, NEG1); bfly<2>(v, NEG1); bfly<4>(v, NEG1);
    bfly<8>(v, NEG1);

    // ---- P2 final stage (i6, reg bit 4) with CZ sign + 2^{-5.5} folded ----
    // i9,i10 = lane bits 3,4 -> sign thread-uniform; (a±b)*sc via 3 ops/pair
    {
        const float S  = 0.022097086912079608f;   // 2^{-5.5}
        float sc = ((lane & 24) == 24) ? -S : S;
        u64 sc2  = pk(sc, sc);
        u64 nsc2 = pk(-sc, -sc);
#pragma unroll
        for (int r = 0; r < 16; r++) {
            u64 a = v[r], b = v[r | 16];
            u64 t = pmul(a, sc2);
            v[r]      = pfma(b, sc2,  t);   // (a+b)*sc
            v[r | 16] = pfma(b, nsc2, t);   // (a-b)*sc
        }
    }
    __syncwarp();   // exch1 reads complete before exch2 writes

    // ---- exch2 write: STS.128 (same slots as exch1 read) ----
    float4* swf4w = (float4*)sw;
#pragma unroll
    for (int k = 0; k < 16; k++) {
        float a, b, c, d;
        upk(v[2 * k], a, b); upk(v[2 * k + 1], c, d);
        swf4w[16 * lane + (k ^ m15)] = make_float4(a, b, c, d);
    }
    __syncwarp();

    // ---- exch2 read: LDS.64 + coalesced streaming STG.128 ----
#pragma unroll
    for (int j = 0; j < 16; j++) {
        int r0 = 2 * j, r1 = 2 * j + 1;
        u64 u0 = sw[32 * r0 + 2 * (colw ^ (r0 & 15)) + h];   // i1 = 0
        u64 u1 = sw[32 * r1 + 2 * (colw ^ (r1 & 15)) + h];   // i1 = 1
        float a, b, c, d;
        upk(u0, a, b); upk(u1, c, d);
        __stcs(&op[lane + 32 * j], make_float4(a, b, c, d));
    }
}

extern "C" void kernel_launch(void* const* d_in, const int* in_sizes, int n_in,
                              void* d_out, int out_size) {
    const float4* in = (const float4*)d_in[0];
    float4* out = (float4*)d_out;
    const int rows = in_sizes[0] / NN;    // 16384
    fwht_cz_kernel<<<rows / 4, 128>>>(in, out, rows);
}